// round 14
// baseline (speedup 1.0000x reference)
#include <cuda_runtime.h>
#include <cuda_bf16.h>
#include <cuda_fp16.h>
#include <cstdint>

// Problem constants
#define B_  8
#define L_  2048
#define E_  1024
#define H_  16
#define D_  64
#define M_  (B_ * L_)        // 16384 rows
#define NBH (B_ * H_)        // 128 head-batches
#define NSPLIT 16
#define LSPL (L_ / NSPLIT)   // 128
#define PI_HALF 1.5707963267948966f

// ---------------- device scratch (no allocations allowed) ----------------
__device__ __half g_qff[(size_t)M_ * H_ * 128];    // qf features, per-head
__device__ __half g_kff[(size_t)M_ * H_ * 128];    // kf features, per-head
__device__ __half g_vf[(size_t)M_ * H_ * 64];      // v fp16, per-head
__device__ __half g_xf[(size_t)M_ * E_];           // X fp16
__device__ __half g_af[(size_t)M_ * E_];           // attn out fp16 (rows l*B+b)
__device__ __half g_wtf[4ull * E_ * E_];           // W^T fp16, per matrix [n][k]
__device__ float g_ksum[NBH * 128];
__device__ float g_P1[NBH * 64];                   // 63*sv - KS1
__device__ float g_P2[NBH * 64];                   // 63*cv - KS2
__device__ float g_Q[NBH * 2];                     // 63*ssum-S1k, 63*csum-S2k
__device__ __half g_kvtf[(size_t)NBH * 64 * 128];  // kv^T [j][i] fp16
// split partials
__device__ __half g_kvp[(size_t)NSPLIT * NBH * 128 * 64];  // fp16 partials
__device__ float g_ksump[NSPLIT * NBH * 128];
__device__ float g_svp[NSPLIT * NBH * 64];
__device__ float g_cvp[NSPLIT * NBH * 64];
__device__ float g_scp[NSPLIT * NBH * 2];

// ---------------- PTX helpers ----------------------------------------------
#define CP16(dst, src) \
    asm volatile("cp.async.cg.shared.global [%0], [%1], 16;" :: "r"(dst), "l"(src))

#define LDSM4(r, addr) \
    asm volatile("ldmatrix.sync.aligned.m8n8.x4.shared.b16 {%0,%1,%2,%3}, [%4];" \
                 : "=r"((r)[0]), "=r"((r)[1]), "=r"((r)[2]), "=r"((r)[3]) : "r"(addr))

#define LDSM4T(r, addr) \
    asm volatile("ldmatrix.sync.aligned.m8n8.x4.trans.shared.b16 {%0,%1,%2,%3}, [%4];" \
                 : "=r"((r)[0]), "=r"((r)[1]), "=r"((r)[2]), "=r"((r)[3]) : "r"(addr))

#define MMA_F16(d, a, b0, b1) \
    asm volatile("mma.sync.aligned.m16n8k16.row.col.f32.f16.f16.f32 " \
                 "{%0,%1,%2,%3},{%4,%5,%6,%7},{%8,%9},{%0,%1,%2,%3};" \
                 : "+f"((d)[0]), "+f"((d)[1]), "+f"((d)[2]), "+f"((d)[3]) \
                 : "r"((a)[0]), "r"((a)[1]), "r"((a)[2]), "r"((a)[3]), \
                   "r"(b0), "r"(b1))

// ---------------- conversions ----------------------------------------------
__global__ __launch_bounds__(256) void convert_x(const float* __restrict__ X) {
    size_t i = ((size_t)blockIdx.x * 256 + threadIdx.x) * 4;
    float4 v = *(const float4*)(X + i);
    *(__half2*)(g_xf + i)     = __floats2half2_rn(v.x, v.y);
    *(__half2*)(g_xf + i + 2) = __floats2half2_rn(v.z, v.w);
}

// transpose: W[k][n] (fp32, n contiguous) -> WT[n][k] fp16
__global__ void convert_w(const float* __restrict__ Wq, const float* __restrict__ Wk,
                          const float* __restrict__ Wv, const float* __restrict__ Wo) {
    const float* W = (blockIdx.z == 0) ? Wq : (blockIdx.z == 1) ? Wk
                   : (blockIdx.z == 2) ? Wv : Wo;
    __shared__ float t[32][33];
    const int nb = blockIdx.x * 32, kb = blockIdx.y * 32;
    const int tx = threadIdx.x, ty = threadIdx.y;
#pragma unroll
    for (int i = 0; i < 4; i++)
        t[ty + 8 * i][tx] = W[(size_t)(kb + ty + 8 * i) * E_ + nb + tx];
    __syncthreads();
    __half* Of = g_wtf + (size_t)blockIdx.z * E_ * E_;
#pragma unroll
    for (int i = 0; i < 4; i++) {
        int n = nb + ty + 8 * i, k = kb + tx;
        Of[(size_t)n * E_ + k] = __float2half(t[tx][ty + 8 * i]);
    }
}

// - fp16 HMMA GEMM core: acc = A[256m] @ B^T[128n], BK=64, 3-stage, 512thr -
#define BK 64
#define STAGES 3
#define TROW 144                        // 64 fp16 = 128B + 16B pad
#define A_TILE_B (256 * TROW)           // 36864
#define B_TILE_B (128 * TROW)           // 18432
#define STAGE_B (A_TILE_B + B_TILE_B)   // 55296
#define DSMEM (STAGES * STAGE_B)        // 165888
#define NCHUNK 16

__device__ __forceinline__ void gemm_core(
    const __half* __restrict__ A, const __half* __restrict__ Bm,
    int mBase, int nBase, float acc[2][8][4])
{
    extern __shared__ char smem[];
    const uint32_t sbase = (uint32_t)__cvta_generic_to_shared(smem);
    const int tid = threadIdx.x;
    const int lane = tid & 31, wid = tid >> 5;
    const int wm = wid & 7, wn = wid >> 3;   // 8 m-warps x 2 n-warps

    // 6 x 16B chunks per thread per stage (A: 2048 chunks, B: 1024 chunks)
    const __half* gp[6];
    uint32_t soff[6];
#pragma unroll
    for (int i = 0; i < 6; i++) {
        const int cid = i * 512 + tid;       // 0..3071
        if (cid < 2048) {                    // A: 256 rows x 8 chunks
            const int row = cid >> 3, ch = cid & 7;
            gp[i]   = A + (size_t)(mBase + row) * E_ + ch * 8;
            soff[i] = (uint32_t)(row * TROW + ch * 16);
        } else {                             // B: 128 rows x 8 chunks
            const int ci = cid - 2048;
            const int row = ci >> 3, ch = ci & 7;
            gp[i]   = Bm + (size_t)(nBase + row) * E_ + ch * 8;
            soff[i] = (uint32_t)(A_TILE_B + row * TROW + ch * 16);
        }
    }

#pragma unroll
    for (int mt = 0; mt < 2; mt++)
#pragma unroll
        for (int nt = 0; nt < 8; nt++)
#pragma unroll
            for (int j = 0; j < 4; j++) acc[mt][nt][j] = 0.f;

    // prologue: chunks 0,1
#pragma unroll
    for (int c = 0; c < 2; c++) {
        const uint32_t sb = sbase + c * STAGE_B;
#pragma unroll
        for (int i = 0; i < 6; i++) CP16(sb + soff[i], gp[i] + c * BK);
        asm volatile("cp.async.commit_group;" ::: "memory");
    }

    for (int c = 0; c < NCHUNK; c++) {
        asm volatile("cp.async.wait_group 1;" ::: "memory");
        __syncthreads();

        if (c + 2 < NCHUNK) {
            const uint32_t sb = sbase + (uint32_t)(((c + 2) % STAGES) * STAGE_B);
            const size_t koff = (size_t)(c + 2) * BK;
#pragma unroll
            for (int i = 0; i < 6; i++) CP16(sb + soff[i], gp[i] + koff);
        }
        asm volatile("cp.async.commit_group;" ::: "memory");

        const uint32_t st = sbase + (uint32_t)((c % STAGES) * STAGE_B);
#pragma unroll
        for (int ks = 0; ks < 4; ks++) {
            uint32_t a[2][4], b[4][4];
            const uint32_t kof = (uint32_t)(ks * 32 + ((lane >> 4) << 4));
#pragma unroll
            for (int mt = 0; mt < 2; mt++) {
                const uint32_t ad = st + (uint32_t)((wm * 32 + mt * 16 + (lane & 15)) * TROW)
                                  + kof;
                LDSM4(a[mt], ad);
            }
#pragma unroll
            for (int nt = 0; nt < 4; nt++) {
                const uint32_t bd = st + A_TILE_B
                                  + (uint32_t)((wn * 64 + nt * 16 + (lane & 15)) * TROW)
                                  + kof;
                LDSM4(b[nt], bd);
            }
#pragma unroll
            for (int mt = 0; mt < 2; mt++)
#pragma unroll
                for (int nt = 0; nt < 4; nt++) {
                    MMA_F16(acc[mt][nt * 2],     a[mt], b[nt][0], b[nt][2]);
                    MMA_F16(acc[mt][nt * 2 + 1], a[mt], b[nt][1], b[nt][3]);
                }
        }
    }
}

// qkv GEMM with fused softmax feature-map epilogue
__global__ __launch_bounds__(512, 1) void qkv_mma(const float* __restrict__ bq,
                                                  const float* __restrict__ bk,
                                                  const float* __restrict__ bv) {
    const int z = blockIdx.z;
    const float* bias = (z == 0) ? bq : (z == 1) ? bk : bv;
    const int mBase = blockIdx.y * 256, nBase = blockIdx.x * 128;

    float acc[2][8][4];
    gemm_core(g_xf, g_wtf + (size_t)z * E_ * E_, mBase, nBase, acc);

    const int tid = threadIdx.x;
    const int lane = tid & 31, wid = tid >> 5;
    const int wm = wid & 7, wn = wid >> 3;
    const int r0 = lane >> 2, cq = (lane & 3) * 2;
    const int head = blockIdx.x * 2 + wn;
    const float angk = PI_HALF / (float)L_;

    float2 bvs[8];
#pragma unroll
    for (int nt8 = 0; nt8 < 8; nt8++)
        bvs[nt8] = *(const float2*)(bias + nBase + wn * 64 + nt8 * 8 + cq);

    if (z < 2) {
        __half* gf = (z == 0) ? g_qff : g_kff;
#pragma unroll
        for (int mt = 0; mt < 2; mt++)
#pragma unroll
            for (int rh = 0; rh < 2; rh++) {
                const int row = mBase + wm * 32 + mt * 16 + r0 + rh * 8;
                float v[8][2];
                float m = -1e30f;
#pragma unroll
                for (int nt8 = 0; nt8 < 8; nt8++) {
                    v[nt8][0] = acc[mt][nt8][rh * 2 + 0] + bvs[nt8].x;
                    v[nt8][1] = acc[mt][nt8][rh * 2 + 1] + bvs[nt8].y;
                    m = fmaxf(m, fmaxf(v[nt8][0], v[nt8][1]));
                }
                m = fmaxf(m, __shfl_xor_sync(0xffffffffu, m, 1));
                m = fmaxf(m, __shfl_xor_sync(0xffffffffu, m, 2));
                float s = 0.f;
#pragma unroll
                for (int nt8 = 0; nt8 < 8; nt8++) {
                    v[nt8][0] = __expf(v[nt8][0] - m);
                    v[nt8][1] = __expf(v[nt8][1] - m);
                    s += v[nt8][0] + v[nt8][1];
                }
                s += __shfl_xor_sync(0xffffffffu, s, 1);
                s += __shfl_xor_sync(0xffffffffu, s, 2);
                const float inv = 1.f / s;
                const int l = row & (L_ - 1);
                float sn, cs;
                __sincosf(angk * (float)(l + 1), &sn, &cs);
                __half* base = gf + ((size_t)row * H_ + head) * 128;
#pragma unroll
                for (int nt8 = 0; nt8 < 8; nt8++) {
                    const int j = nt8 * 8 + cq;
                    const float a0 = v[nt8][0] * inv, a1 = v[nt8][1] * inv;
                    *(__half2*)(base + j)      = __floats2half2_rn(a0 * sn, a1 * sn);
                    *(__half2*)(base + j + 64) = __floats2half2_rn(a0 * cs, a1 * cs);
                }
            }
    } else {
#pragma unroll
        for (int mt = 0; mt < 2; mt++)
#pragma unroll
            for (int nt8 = 0; nt8 < 8; nt8++) {
                const int j = nt8 * 8 + cq;
                const int row = mBase + wm * 32 + mt * 16 + r0;
                __half* p0 = g_vf + ((size_t)row * H_ + head) * 64 + j;
                *(__half2*)p0 = __floats2half2_rn(acc[mt][nt8][0] + bvs[nt8].x,
                                                  acc[mt][nt8][1] + bvs[nt8].y);
                __half* p1 = g_vf + ((size_t)(row + 8) * H_ + head) * 64 + j;
                *(__half2*)p1 = __floats2half2_rn(acc[mt][nt8][2] + bvs[nt8].x,
                                                  acc[mt][nt8][3] + bvs[nt8].y);
            }
    }
}

__global__ __launch_bounds__(512, 1) void oproj_mma(const float* __restrict__ bo,
                                                    float* __restrict__ out) {
    const int mBase = blockIdx.y * 256, nBase = blockIdx.x * 128;
    float acc[2][8][4];
    gemm_core(g_af, g_wtf + 3ull * E_ * E_, mBase, nBase, acc);

    const int tid = threadIdx.x;
    const int lane = tid & 31, wid = tid >> 5;
    const int wm = wid & 7, wn = wid >> 3;
    const int r0 = lane >> 2, cq = (lane & 3) * 2;
#pragma unroll
    for (int mt = 0; mt < 2; mt++)
#pragma unroll
        for (int nt8 = 0; nt8 < 8; nt8++) {
            const int col = nBase + wn * 64 + nt8 * 8 + cq;
            const float2 bv = *(const float2*)(bo + col);
            const int row = mBase + wm * 32 + mt * 16 + r0;
            float* cp0 = out + (size_t)row * E_ + col;
            *(float2*)cp0 = make_float2(acc[mt][nt8][0] + bv.x, acc[mt][nt8][1] + bv.y);
            float* cp1 = cp0 + 8 * E_;
            *(float2*)cp1 = make_float2(acc[mt][nt8][2] + bv.x, acc[mt][nt8][3] + bv.y);
        }
}

// ---------------- KV reduction via HMMA (split over L) ---------------------
#define KV_KF   0                      // 128 * 272 = 34816
#define KV_VV   34816                  // 128 * 144 = 18432 -> 53248
#define KV_SN   53248
#define KV_CS   53760
#define KV_SMEM 54272

__global__ __launch_bounds__(256) void kv_reduce_part() {
    extern __shared__ char sm[];
    const uint32_t sbase = (uint32_t)__cvta_generic_to_shared(sm);
    const int bh = blockIdx.x;
    const int sp = blockIdx.y;
    const int b = bh / H_, h = bh % H_;
    const int pbase = sp * NBH + bh;

    const int t = threadIdx.x;
    const int w = t >> 5, lane = t & 31;

    __half* kf_s = (__half*)(sm + KV_KF);
    __half* v_s  = (__half*)(sm + KV_VV);
    float* sn_s  = (float*)(sm + KV_SN);
    float* cs_s  = (float*)(sm + KV_CS);

    {
        const __half* kfb = g_kff + (((size_t)b * L_ + sp * LSPL) * H_ + h) * 128;
        const __half* vb  = g_vf  + (((size_t)b * L_ + sp * LSPL) * H_ + h) * 64;
#pragma unroll
        for (int i = 0; i < 8; i++) {
            const int c = i * 256 + t;
            const int row = c >> 4, ch = c & 15;
            CP16(sbase + KV_KF + row * 272 + ch * 16, kfb + (size_t)row * 2048 + ch * 8);
        }
#pragma unroll
        for (int i = 0; i < 4; i++) {
            const int c = i * 256 + t;
            const int row = c >> 3, ch = c & 7;
            CP16(sbase + KV_VV + row * 144 + ch * 16, vb + (size_t)row * 1024 + ch * 8);
        }
        asm volatile("cp.async.commit_group;" ::: "memory");
    }
    if (t < 128) {
        float sn, cs;
        __sincosf(PI_HALF / (float)L_ * (float)(sp * LSPL + t + 1), &sn, &cs);
        sn_s[t] = sn;
        cs_s[t] = cs;
    }
    asm volatile("cp.async.wait_group 0;" ::: "memory");
    __syncthreads();

    if (t < 128) {
        float s = 0.f;
#pragma unroll 8
        for (int row = 0; row < 128; row++)
            s += __half2float(kf_s[row * 136 + t]);
        g_ksump[pbase * 128 + t] = s;
        if (t < 2) {
            const float* src = (t == 0) ? sn_s : cs_s;
            float acc = 0.f;
#pragma unroll 8
            for (int row = 0; row < 128; row++) acc += src[row];
            g_scp[pbase * 2 + t] = acc;
        }
    } else if (t < 192) {
        const int col = t - 128;
        float s = 0.f;
#pragma unroll 8
        for (int row = 0; row < 128; row++)
            s += sn_s[row] * __half2float(v_s[row * 72 + col]);
        g_svp[pbase * 64 + col] = s;
    } else {
        const int col = t - 192;
        float s = 0.f;
#pragma unroll 8
        for (int row = 0; row < 128; row++)
            s += cs_s[row] * __half2float(v_s[row * 72 + col]);
        g_cvp[pbase * 64 + col] = s;
    }

    // phase 2: kv[i][j] = sum_l kf[l][i] v[l][j] via trans-ldmatrix MMA
    const int wm = w & 3, wn = w >> 2;
    const int m_base = wm * 32, n_base = wn * 32;
    float acc[2][4][4];
#pragma unroll
    for (int mt = 0; mt < 2; mt++)
#pragma unroll
        for (int nb = 0; nb < 4; nb++)
#pragma unroll
            for (int j = 0; j < 4; j++) acc[mt][nb][j] = 0.f;

    const int krow = (lane & 7) + ((lane >> 4) << 3);
    const int csel = (lane & 8);
#pragma unroll
    for (int kc = 0; kc < 8; kc++) {
        const int kb = kc * 16;
        uint32_t a[2][4], bb[2][4];
#pragma unroll
        for (int mt = 0; mt < 2; mt++) {
            const uint32_t ad = sbase + KV_KF
                + (uint32_t)((kb + krow) * 272 + (m_base + mt * 16 + csel) * 2);
            LDSM4T(a[mt], ad);
        }
#pragma unroll
        for (int nt = 0; nt < 2; nt++) {
            const uint32_t bd = sbase + KV_VV
                + (uint32_t)((kb + krow) * 144 + (n_base + nt * 16 + csel) * 2);
            LDSM4T(bb[nt], bd);
        }
#pragma unroll
        for (int mt = 0; mt < 2; mt++)
#pragma unroll
            for (int nt = 0; nt < 2; nt++) {
                MMA_F16(acc[mt][nt * 2],     a[mt], bb[nt][0], bb[nt][2]);
                MMA_F16(acc[mt][nt * 2 + 1], a[mt], bb[nt][1], bb[nt][3]);
            }
    }

    __half* KVp = g_kvp + (size_t)pbase * 8192;
    const int r0 = lane >> 2, cq = (lane & 3) * 2;
#pragma unroll
    for (int mt = 0; mt < 2; mt++)
#pragma unroll
        for (int nb = 0; nb < 4; nb++) {
            const int i0 = m_base + mt * 16 + r0;
            const int j = n_base + nb * 8 + cq;
            *(__half2*)(KVp + i0 * 64 + j) =
                __floats2half2_rn(acc[mt][nb][0], acc[mt][nb][1]);
            *(__half2*)(KVp + (i0 + 8) * 64 + j) =
                __floats2half2_rn(acc[mt][nb][2], acc[mt][nb][3]);
        }
}

// combine partials; derive P1/P2/Q; emit kv^T fp16 for the apply MMA
__global__ __launch_bounds__(256) void kv_combine() {
    const int bh = blockIdx.x;
    const int t = threadIdx.x;

    __shared__ float kv_s[128 * 64];
    __shared__ float ksum_s[128];
    __shared__ float sv_s[64], cv_s[64];

    {
        float s[32];
#pragma unroll
        for (int i = 0; i < 32; i++) s[i] = 0.f;
        const int e0 = t * 32;
#pragma unroll
        for (int p = 0; p < NSPLIT; p++) {
            const __half* base = g_kvp + (size_t)(p * NBH + bh) * 8192 + e0;
#pragma unroll
            for (int c = 0; c < 4; c++) {
                uint4 u = *(const uint4*)(base + c * 8);
                float2 f;
                f = __half22float2(*(__half2*)&u.x); s[c*8+0] += f.x; s[c*8+1] += f.y;
                f = __half22float2(*(__half2*)&u.y); s[c*8+2] += f.x; s[c*8+3] += f.y;
                f = __half22float2(*(__half2*)&u.z); s[c*8+4] += f.x; s[c*8+5] += f.y;
                f = __half22float2(*(__half2*)&u.w); s[c*8+6] += f.x; s[c*8+7] += f.y;
            }
        }
#pragma unroll
        for (int c = 0; c < 8; c++)
            *(float4*)(kv_s + e0 + c * 4) =
                make_float4(s[c*4], s[c*4+1], s[c*4+2], s[c*4+3]);
    }
    if (t < 128) {
        float s = 0.f;
#pragma unroll
        for (int p = 0; p < NSPLIT; p++) s += g_ksump[(p * NBH + bh) * 128 + t];
        ksum_s[t] = s;
        g_ksum[bh * 128 + t] = s;
    } else if (t < 192) {
        float s = 0.f;
#pragma unroll
        for (int p = 0; p < NSPLIT; p++) s += g_svp[(p * NBH + bh) * 64 + t - 128];
        sv_s[t - 128] = s;
    } else {
        float s = 0.f;
#pragma unroll
        for (int p = 0; p < NSPLIT; p++) s += g_cvp[(p * NBH + bh) * 64 + t - 192];
        cv_s[t - 192] = s;
    }
    __syncthreads();

    {
        const int j = t & 63;
        const int i0 = (t >> 6) * 32;
        __half* Of = g_kvtf + (size_t)bh * 8192 + j * 128;
#pragma unroll 4
        for (int i = i0; i < i0 + 32; i += 2) {
            float a = kv_s[i * 64 + j];
            float c = kv_s[(i + 1) * 64 + j];
            *(__half2*)(Of + i) = __floats2half2_rn(a, c);
        }
    }

    if (t < 64) {
        float ks1 = 0.f;
#pragma unroll 8
        for (int i = 0; i < 64; i++) ks1 += kv_s[i * 64 + t];
        g_P1[bh * 64 + t] = 63.f * sv_s[t] - ks1;
    } else if (t < 128) {
        const int j = t - 64;
        float ks2 = 0.f;
#pragma unroll 8
        for (int i = 64; i < 128; i++) ks2 += kv_s[i * 64 + j];
        g_P2[bh * 64 + j] = 63.f * cv_s[j] - ks2;
    } else if (t == 128) {
        float s1k = 0.f;
        for (int i = 0; i < 64; i++) s1k += ksum_s[i];
        float ss = 0.f;
        for (int p = 0; p < NSPLIT; p++) ss += g_scp[(p * NBH + bh) * 2];
        g_Q[bh * 2] = 63.f * ss - s1k;
    } else if (t == 129) {
        float s2k = 0.f;
        for (int i = 64; i < 128; i++) s2k += ksum_s[i];
        float cc = 0.f;
        for (int p = 0; p < NSPLIT; p++) cc += g_scp[(p * NBH + bh) * 2 + 1];
        g_Q[bh * 2 + 1] = 63.f * cc - s2k;
    }
}

// ---------------- apply via fp16 HMMA: C = qf @ kv^T, then normalize -------
#define OFF_QF   0
#define OFF_KT   34816
#define OFF_KSUM 52224
#define OFF_P1   (OFF_KSUM + 512)
#define OFF_P2   (OFF_P1 + 256)
#define OFF_ZZ   (OFF_P2 + 256)
#define OFF_Z2   (OFF_ZZ + 512)
#define OFF_SN   (OFF_Z2 + 512)
#define OFF_CS   (OFF_SN + 512)
#define ATTN_SMEM (OFF_CS + 512)   // 55296

__global__ __launch_bounds__(256) void attn_apply() {
    extern __shared__ char sm[];
    const uint32_t sbase = (uint32_t)__cvta_generic_to_shared(sm);
    const int bh = blockIdx.x;
    const int b = bh / H_, h = bh % H_;
    const int lbase = blockIdx.y * 128;
    const int t = threadIdx.x;
    const int w = t >> 5, lane = t & 31;

    float* ksum_s = (float*)(sm + OFF_KSUM);
    float* P1_s   = (float*)(sm + OFF_P1);
    float* P2_s   = (float*)(sm + OFF_P2);
    float* zz_s   = (float*)(sm + OFF_ZZ);
    float* z2_s   = (float*)(sm + OFF_Z2);
    float* sn_s   = (float*)(sm + OFF_SN);
    float* cs_s   = (float*)(sm + OFF_CS);

    {
        const __half* qfb = g_qff + (((size_t)b * L_ + lbase) * H_ + h) * 128;
#pragma unroll
        for (int i = 0; i < 8; i++) {
            const int c = i * 256 + t;
            const int row = c >> 4, ch = c & 15;
            CP16(sbase + OFF_QF + row * 272 + ch * 16, qfb + (size_t)row * 2048 + ch * 8);
        }
        const __half* Gf = g_kvtf + (size_t)bh * 8192;
#pragma unroll
        for (int i = 0; i < 4; i++) {
            const int c = i * 256 + t;
            const int row = c >> 4, ch = c & 15;
            CP16(sbase + OFF_KT + row * 272 + ch * 16, Gf + c * 8);
        }
        asm volatile("cp.async.commit_group;" ::: "memory");
        if (t < 128) ksum_s[t] = g_ksum[bh * 128 + t];
        else if (t < 192) P1_s[t - 128] = g_P1[bh * 64 + t - 128];
        else P2_s[t - 192] = g_P2[bh * 64 + t - 192];
    }
    const float Q1 = g_Q[bh * 2], Q2 = g_Q[bh * 2 + 1];
    const float angk = PI_HALF / (float)L_;
    asm volatile("cp.async.wait_group 0;" ::: "memory");
    __syncthreads();

    const __half* qf = (const __half*)(sm + OFF_QF);

#pragma unroll 1
    for (int r = 0; r < 16; r++) {
        const int row = w * 16 + r;
        float f0 = __half2float(qf[row * 136 + lane]);
        float f1 = __half2float(qf[row * 136 + lane + 32]);
        float f2 = __half2float(qf[row * 136 + lane + 64]);
        float f3 = __half2float(qf[row * 136 + lane + 96]);
        float d1 = f0 * ksum_s[lane] + f1 * ksum_s[lane + 32] +
                   f2 * ksum_s[lane + 64] + f3 * ksum_s[lane + 96];
#pragma unroll
        for (int o = 16; o; o >>= 1) d1 += __shfl_xor_sync(0xffffffffu, d1, o);
        if (lane == 0) {
            float sn, cs;
            __sincosf(angk * (float)(lbase + row + 1), &sn, &cs);
            float z1 = 1.f / fmaxf(d1, 1e-6f);
            float d2 = sn * Q1 + cs * Q2 + d1;
            float z2 = 1.f / fmaxf(d2, 1e-6f);
            zz_s[row] = z1 + z2;
            z2_s[row] = z2;
            sn_s[row] = sn;
            cs_s[row] = cs;
        }
    }
    __syncthreads();

    const int m0 = w * 16;
    float acc[8][4];
#pragma unroll
    for (int nt = 0; nt < 8; nt++)
#pragma unroll
        for (int j = 0; j < 4; j++) acc[nt][j] = 0.f;

    const uint32_t aoffB = sbase + OFF_QF
        + (uint32_t)((m0 + (lane & 15)) * 272 + (lane >> 4) * 16);
    const uint32_t boffB = sbase + OFF_KT
        + (uint32_t)((lane & 15) * 272 + (lane >> 4) * 16);
#pragma unroll
    for (int ks = 0; ks < 8; ks++) {
        uint32_t a[4], bb[4][4];
        LDSM4(a, aoffB + ks * 32);
#pragma unroll
        for (int nt = 0; nt < 4; nt++)
            LDSM4(bb[nt], boffB + nt * 16 * 272 + ks * 32);
#pragma unroll
        for (int nt = 0; nt < 4; nt++) {
            MMA_F16(acc[nt * 2],     a, bb[nt][0], bb[nt][2]);
            MMA_F16(acc[nt * 2 + 1], a, bb[nt][1], bb[nt][3]);
        }
    }

    const int r0 = lane >> 2, cq = (lane & 3) * 2;
#pragma unroll
    for (int nt8 = 0; nt8 < 8; nt8++) {
        const int j = nt8 * 8 + cq;
        const float p1x = P1_s[j], p1y = P1_s[j + 1];
        const float p2x = P2_s[j], p2y = P2_s[j + 1];
#pragma unroll
        for (int half_ = 0; half_ < 2; half_++) {
            const int row = m0 + r0 + half_ * 8;
            const float oz = zz_s[row], o2 = z2_s[row];
            const float sr = sn_s[row], cr = cs_s[row];
            const float px = sr * p1x + cr * p2x;
            const float py = sr * p1y + cr * p2y;
            float o0 = oz * acc[nt8][half_ * 2 + 0] + o2 * px;
            float o1 = oz * acc[nt8][half_ * 2 + 1] + o2 * py;
            const int posl = lbase + row;
            const size_t oidx = ((size_t)posl * B_ + b) * E_ + h * D_ + j;
            *(__half2*)(g_af + oidx) = __floats2half2_rn(o0, o1);
        }
    }
}

// ---------------- launch ----------------------------------------------------
extern "C" void kernel_launch(void* const* d_in, const int* in_sizes, int n_in,
                              void* d_out, int out_size) {
    const float* X  = (const float*)d_in[0];
    const float* Wq = (const float*)d_in[1];
    const float* bq = (const float*)d_in[2];
    const float* Wk = (const float*)d_in[3];
    const float* bk = (const float*)d_in[4];
    const float* Wv = (const float*)d_in[5];
    const float* bv = (const float*)d_in[6];
    const float* Wo = (const float*)d_in[7];
    const float* bo = (const float*)d_in[8];
    float* out = (float*)d_out;

    cudaFuncSetAttribute(qkv_mma, cudaFuncAttributeMaxDynamicSharedMemorySize, DSMEM);
    cudaFuncSetAttribute(oproj_mma, cudaFuncAttributeMaxDynamicSharedMemorySize, DSMEM);
    cudaFuncSetAttribute(attn_apply, cudaFuncAttributeMaxDynamicSharedMemorySize, ATTN_SMEM);
    cudaFuncSetAttribute(kv_reduce_part, cudaFuncAttributeMaxDynamicSharedMemorySize, KV_SMEM);

    convert_x<<<(M_ * E_) / (256 * 4), 256>>>(X);
    convert_w<<<dim3(32, 32, 4), dim3(32, 8)>>>(Wq, Wk, Wv, Wo);
    qkv_mma<<<dim3(8, 64, 3), 512, DSMEM>>>(bq, bk, bv);
    kv_reduce_part<<<dim3(NBH, NSPLIT), 256, KV_SMEM>>>();
    kv_combine<<<NBH, 256>>>();
    attn_apply<<<dim3(NBH, L_ / 128), 256, ATTN_SMEM>>>();
    oproj_mma<<<dim3(8, 64), 512, DSMEM>>>(bo, out);
}

// round 15
// speedup vs baseline: 1.6140x; 1.6140x over previous
#include <cuda_runtime.h>
#include <cuda_bf16.h>
#include <cuda_fp16.h>
#include <cstdint>

// Problem constants
#define B_  8
#define L_  2048
#define E_  1024
#define H_  16
#define D_  64
#define M_  (B_ * L_)        // 16384 rows
#define NBH (B_ * H_)        // 128 head-batches
#define NSPLIT 16
#define LSPL (L_ / NSPLIT)   // 128
#define PI_HALF 1.5707963267948966f

// ---------------- device scratch (no allocations allowed) ----------------
__device__ __half g_qff[(size_t)M_ * H_ * 128];    // qf features, per-head
__device__ __half g_kff[(size_t)M_ * H_ * 128];    // kf features, per-head
__device__ __half g_vf[(size_t)M_ * H_ * 64];      // v fp16, per-head
__device__ __half g_xf[(size_t)M_ * E_];           // X fp16
__device__ __half g_af[(size_t)M_ * E_];           // attn out fp16 (rows l*B+b)
__device__ __half g_wtf[4ull * E_ * E_];           // W^T fp16, per matrix [n][k]
__device__ float g_ksum[NBH * 128];
__device__ float g_P1[NBH * 64];                   // 63*sv - KS1
__device__ float g_P2[NBH * 64];                   // 63*cv - KS2
__device__ float g_Q[NBH * 2];                     // 63*ssum-S1k, 63*csum-S2k
__device__ __half g_kvtf[(size_t)NBH * 64 * 128];  // kv^T [j][i] fp16
// split partials
__device__ __half g_kvp[(size_t)NSPLIT * NBH * 128 * 64];  // fp16 partials
__device__ float g_ksump[NSPLIT * NBH * 128];
__device__ float g_svp[NSPLIT * NBH * 64];
__device__ float g_cvp[NSPLIT * NBH * 64];
__device__ float g_scp[NSPLIT * NBH * 2];

// ---------------- PTX helpers ----------------------------------------------
#define CP16(dst, src) \
    asm volatile("cp.async.cg.shared.global [%0], [%1], 16;" :: "r"(dst), "l"(src))

#define LDSM4(r, addr) \
    asm volatile("ldmatrix.sync.aligned.m8n8.x4.shared.b16 {%0,%1,%2,%3}, [%4];" \
                 : "=r"((r)[0]), "=r"((r)[1]), "=r"((r)[2]), "=r"((r)[3]) : "r"(addr))

#define LDSM4T(r, addr) \
    asm volatile("ldmatrix.sync.aligned.m8n8.x4.trans.shared.b16 {%0,%1,%2,%3}, [%4];" \
                 : "=r"((r)[0]), "=r"((r)[1]), "=r"((r)[2]), "=r"((r)[3]) : "r"(addr))

#define MMA_F16(d, a, b0, b1) \
    asm volatile("mma.sync.aligned.m16n8k16.row.col.f32.f16.f16.f32 " \
                 "{%0,%1,%2,%3},{%4,%5,%6,%7},{%8,%9},{%0,%1,%2,%3};" \
                 : "+f"((d)[0]), "+f"((d)[1]), "+f"((d)[2]), "+f"((d)[3]) \
                 : "r"((a)[0]), "r"((a)[1]), "r"((a)[2]), "r"((a)[3]), \
                   "r"(b0), "r"(b1))

// ---------------- conversions ----------------------------------------------
__global__ __launch_bounds__(256) void convert_x(const float* __restrict__ X) {
    size_t i = ((size_t)blockIdx.x * 256 + threadIdx.x) * 4;
    float4 v = *(const float4*)(X + i);
    *(__half2*)(g_xf + i)     = __floats2half2_rn(v.x, v.y);
    *(__half2*)(g_xf + i + 2) = __floats2half2_rn(v.z, v.w);
}

// transpose: W[k][n] (fp32, n contiguous) -> WT[n][k] fp16
__global__ void convert_w(const float* __restrict__ Wq, const float* __restrict__ Wk,
                          const float* __restrict__ Wv, const float* __restrict__ Wo) {
    const float* W = (blockIdx.z == 0) ? Wq : (blockIdx.z == 1) ? Wk
                   : (blockIdx.z == 2) ? Wv : Wo;
    __shared__ float t[32][33];
    const int nb = blockIdx.x * 32, kb = blockIdx.y * 32;
    const int tx = threadIdx.x, ty = threadIdx.y;
#pragma unroll
    for (int i = 0; i < 4; i++)
        t[ty + 8 * i][tx] = W[(size_t)(kb + ty + 8 * i) * E_ + nb + tx];
    __syncthreads();
    __half* Of = g_wtf + (size_t)blockIdx.z * E_ * E_;
#pragma unroll
    for (int i = 0; i < 4; i++) {
        int n = nb + ty + 8 * i, k = kb + tx;
        Of[(size_t)n * E_ + k] = __float2half(t[tx][ty + 8 * i]);
    }
}

// ---- fp16 HMMA GEMM core: acc = A[128m] @ B^T[128n], BK=64, 3-stage ------
#define BK 64
#define STAGES 3
#define TROW 144                       // 64 fp16 = 128B + 16B pad
#define TILE_BYTES (128 * TROW)        // 18432
#define STAGE_B (2 * TILE_BYTES)       // 36864
#define DSMEM (STAGES * STAGE_B)       // 110592
#define NCHUNK 16

__device__ __forceinline__ void gemm_core(
    const __half* __restrict__ A, const __half* __restrict__ Bm,
    int mBase, int nBase, float acc[2][8][4])
{
    extern __shared__ char smem[];
    const uint32_t sbase = (uint32_t)__cvta_generic_to_shared(smem);
    const int tid = threadIdx.x;
    const int lane = tid & 31, wid = tid >> 5;
    const int wm = wid & 3, wn = wid >> 2;

    // 8 x 16B chunks per thread per stage (2 tiles of 128 rows x 8 chunks)
    const __half* gp[8];
    uint32_t soff[8];
#pragma unroll
    for (int i = 0; i < 8; i++) {
        const int cid  = i * 256 + tid;      // 0..2047
        const int tile = cid >> 10;
        const int ci   = cid & 1023;
        const int row  = ci >> 3;
        const int ch   = ci & 7;
        const __half* base = (tile == 0) ? A : Bm;
        const int grow = ((tile == 0) ? mBase : nBase) + row;
        gp[i]   = base + (size_t)grow * E_ + ch * 8;
        soff[i] = (uint32_t)(tile * TILE_BYTES + row * TROW + ch * 16);
    }

#pragma unroll
    for (int mt = 0; mt < 2; mt++)
#pragma unroll
        for (int nt = 0; nt < 8; nt++)
#pragma unroll
            for (int j = 0; j < 4; j++) acc[mt][nt][j] = 0.f;

    // prologue: chunks 0,1
#pragma unroll
    for (int c = 0; c < 2; c++) {
        const uint32_t sb = sbase + c * STAGE_B;
#pragma unroll
        for (int i = 0; i < 8; i++) CP16(sb + soff[i], gp[i] + c * BK);
        asm volatile("cp.async.commit_group;" ::: "memory");
    }

    for (int c = 0; c < NCHUNK; c++) {
        asm volatile("cp.async.wait_group 1;" ::: "memory");
        __syncthreads();

        if (c + 2 < NCHUNK) {
            const uint32_t sb = sbase + (uint32_t)(((c + 2) % STAGES) * STAGE_B);
            const size_t koff = (size_t)(c + 2) * BK;
#pragma unroll
            for (int i = 0; i < 8; i++) CP16(sb + soff[i], gp[i] + koff);
        }
        asm volatile("cp.async.commit_group;" ::: "memory");

        const uint32_t st = sbase + (uint32_t)((c % STAGES) * STAGE_B);
#pragma unroll
        for (int ks = 0; ks < 4; ks++) {
            uint32_t a[2][4], b[4][4];
            const uint32_t kof = (uint32_t)(ks * 32 + ((lane >> 4) << 4));
#pragma unroll
            for (int mt = 0; mt < 2; mt++) {
                const uint32_t ad = st + (uint32_t)((wm * 32 + mt * 16 + (lane & 15)) * TROW)
                                  + kof;
                LDSM4(a[mt], ad);
            }
#pragma unroll
            for (int nt = 0; nt < 4; nt++) {
                const uint32_t bd = st + TILE_BYTES
                                  + (uint32_t)((wn * 64 + nt * 16 + (lane & 15)) * TROW)
                                  + kof;
                LDSM4(b[nt], bd);
            }
#pragma unroll
            for (int mt = 0; mt < 2; mt++)
#pragma unroll
                for (int nt = 0; nt < 4; nt++) {
                    MMA_F16(acc[mt][nt * 2],     a[mt], b[nt][0], b[nt][2]);
                    MMA_F16(acc[mt][nt * 2 + 1], a[mt], b[nt][1], b[nt][3]);
                }
        }
    }
}

// qkv GEMM with fused softmax feature-map epilogue
__global__ __launch_bounds__(256, 2) void qkv_mma(const float* __restrict__ bq,
                                                  const float* __restrict__ bk,
                                                  const float* __restrict__ bv) {
    const int z = blockIdx.z;
    const float* bias = (z == 0) ? bq : (z == 1) ? bk : bv;
    const int mBase = blockIdx.y * 128, nBase = blockIdx.x * 128;

    float acc[2][8][4];
    gemm_core(g_xf, g_wtf + (size_t)z * E_ * E_, mBase, nBase, acc);

    const int tid = threadIdx.x;
    const int lane = tid & 31, wid = tid >> 5;
    const int wm = wid & 3, wn = wid >> 2;
    const int r0 = lane >> 2, cq = (lane & 3) * 2;
    const int head = blockIdx.x * 2 + wn;
    const float angk = PI_HALF / (float)L_;

    float2 bvs[8];
#pragma unroll
    for (int nt8 = 0; nt8 < 8; nt8++)
        bvs[nt8] = *(const float2*)(bias + nBase + wn * 64 + nt8 * 8 + cq);

    if (z < 2) {
        __half* gf = (z == 0) ? g_qff : g_kff;
#pragma unroll
        for (int mt = 0; mt < 2; mt++)
#pragma unroll
            for (int rh = 0; rh < 2; rh++) {
                const int row = mBase + wm * 32 + mt * 16 + r0 + rh * 8;
                float v[8][2];
                float m = -1e30f;
#pragma unroll
                for (int nt8 = 0; nt8 < 8; nt8++) {
                    v[nt8][0] = acc[mt][nt8][rh * 2 + 0] + bvs[nt8].x;
                    v[nt8][1] = acc[mt][nt8][rh * 2 + 1] + bvs[nt8].y;
                    m = fmaxf(m, fmaxf(v[nt8][0], v[nt8][1]));
                }
                m = fmaxf(m, __shfl_xor_sync(0xffffffffu, m, 1));
                m = fmaxf(m, __shfl_xor_sync(0xffffffffu, m, 2));
                float s = 0.f;
#pragma unroll
                for (int nt8 = 0; nt8 < 8; nt8++) {
                    v[nt8][0] = __expf(v[nt8][0] - m);
                    v[nt8][1] = __expf(v[nt8][1] - m);
                    s += v[nt8][0] + v[nt8][1];
                }
                s += __shfl_xor_sync(0xffffffffu, s, 1);
                s += __shfl_xor_sync(0xffffffffu, s, 2);
                const float inv = 1.f / s;
                const int l = row & (L_ - 1);
                float sn, cs;
                __sincosf(angk * (float)(l + 1), &sn, &cs);
                __half* base = gf + ((size_t)row * H_ + head) * 128;
#pragma unroll
                for (int nt8 = 0; nt8 < 8; nt8++) {
                    const int j = nt8 * 8 + cq;
                    const float a0 = v[nt8][0] * inv, a1 = v[nt8][1] * inv;
                    *(__half2*)(base + j)      = __floats2half2_rn(a0 * sn, a1 * sn);
                    *(__half2*)(base + j + 64) = __floats2half2_rn(a0 * cs, a1 * cs);
                }
            }
    } else {
#pragma unroll
        for (int mt = 0; mt < 2; mt++)
#pragma unroll
            for (int nt8 = 0; nt8 < 8; nt8++) {
                const int j = nt8 * 8 + cq;
                const int row = mBase + wm * 32 + mt * 16 + r0;
                __half* p0 = g_vf + ((size_t)row * H_ + head) * 64 + j;
                *(__half2*)p0 = __floats2half2_rn(acc[mt][nt8][0] + bvs[nt8].x,
                                                  acc[mt][nt8][1] + bvs[nt8].y);
                __half* p1 = g_vf + ((size_t)(row + 8) * H_ + head) * 64 + j;
                *(__half2*)p1 = __floats2half2_rn(acc[mt][nt8][2] + bvs[nt8].x,
                                                  acc[mt][nt8][3] + bvs[nt8].y);
            }
    }
}

__global__ __launch_bounds__(256, 2) void oproj_mma(const float* __restrict__ bo,
                                                    float* __restrict__ out) {
    const int mBase = blockIdx.y * 128, nBase = blockIdx.x * 128;
    float acc[2][8][4];
    gemm_core(g_af, g_wtf + 3ull * E_ * E_, mBase, nBase, acc);

    const int tid = threadIdx.x;
    const int lane = tid & 31, wid = tid >> 5;
    const int wm = wid & 3, wn = wid >> 2;
    const int r0 = lane >> 2, cq = (lane & 3) * 2;
#pragma unroll
    for (int mt = 0; mt < 2; mt++)
#pragma unroll
        for (int nt8 = 0; nt8 < 8; nt8++) {
            const int col = nBase + wn * 64 + nt8 * 8 + cq;
            const float2 bv = *(const float2*)(bo + col);
            const int row = mBase + wm * 32 + mt * 16 + r0;
            float* cp0 = out + (size_t)row * E_ + col;
            *(float2*)cp0 = make_float2(acc[mt][nt8][0] + bv.x, acc[mt][nt8][1] + bv.y);
            float* cp1 = cp0 + 8 * E_;
            *(float2*)cp1 = make_float2(acc[mt][nt8][2] + bv.x, acc[mt][nt8][3] + bv.y);
        }
}

// ---------------- KV reduction via HMMA (split over L) ---------------------
#define KV_KF   0                      // 128 * 272 = 34816
#define KV_VV   34816                  // 128 * 144 = 18432 -> 53248
#define KV_SN   53248
#define KV_CS   53760
#define KV_SMEM 54272

__global__ __launch_bounds__(256) void kv_reduce_part() {
    extern __shared__ char sm[];
    const uint32_t sbase = (uint32_t)__cvta_generic_to_shared(sm);
    const int bh = blockIdx.x;
    const int sp = blockIdx.y;
    const int b = bh / H_, h = bh % H_;
    const int pbase = sp * NBH + bh;

    const int t = threadIdx.x;
    const int w = t >> 5, lane = t & 31;

    __half* kf_s = (__half*)(sm + KV_KF);
    __half* v_s  = (__half*)(sm + KV_VV);
    float* sn_s  = (float*)(sm + KV_SN);
    float* cs_s  = (float*)(sm + KV_CS);

    {
        const __half* kfb = g_kff + (((size_t)b * L_ + sp * LSPL) * H_ + h) * 128;
        const __half* vb  = g_vf  + (((size_t)b * L_ + sp * LSPL) * H_ + h) * 64;
#pragma unroll
        for (int i = 0; i < 8; i++) {
            const int c = i * 256 + t;
            const int row = c >> 4, ch = c & 15;
            CP16(sbase + KV_KF + row * 272 + ch * 16, kfb + (size_t)row * 2048 + ch * 8);
        }
#pragma unroll
        for (int i = 0; i < 4; i++) {
            const int c = i * 256 + t;
            const int row = c >> 3, ch = c & 7;
            CP16(sbase + KV_VV + row * 144 + ch * 16, vb + (size_t)row * 1024 + ch * 8);
        }
        asm volatile("cp.async.commit_group;" ::: "memory");
    }
    if (t < 128) {
        float sn, cs;
        __sincosf(PI_HALF / (float)L_ * (float)(sp * LSPL + t + 1), &sn, &cs);
        sn_s[t] = sn;
        cs_s[t] = cs;
    }
    asm volatile("cp.async.wait_group 0;" ::: "memory");
    __syncthreads();

    if (t < 128) {
        float s = 0.f;
#pragma unroll 8
        for (int row = 0; row < 128; row++)
            s += __half2float(kf_s[row * 136 + t]);
        g_ksump[pbase * 128 + t] = s;
        if (t < 2) {
            const float* src = (t == 0) ? sn_s : cs_s;
            float acc = 0.f;
#pragma unroll 8
            for (int row = 0; row < 128; row++) acc += src[row];
            g_scp[pbase * 2 + t] = acc;
        }
    } else if (t < 192) {
        const int col = t - 128;
        float s = 0.f;
#pragma unroll 8
        for (int row = 0; row < 128; row++)
            s += sn_s[row] * __half2float(v_s[row * 72 + col]);
        g_svp[pbase * 64 + col] = s;
    } else {
        const int col = t - 192;
        float s = 0.f;
#pragma unroll 8
        for (int row = 0; row < 128; row++)
            s += cs_s[row] * __half2float(v_s[row * 72 + col]);
        g_cvp[pbase * 64 + col] = s;
    }

    // phase 2: kv[i][j] = sum_l kf[l][i] v[l][j] via trans-ldmatrix MMA
    const int wm = w & 3, wn = w >> 2;
    const int m_base = wm * 32, n_base = wn * 32;
    float acc[2][4][4];
#pragma unroll
    for (int mt = 0; mt < 2; mt++)
#pragma unroll
        for (int nb = 0; nb < 4; nb++)
#pragma unroll
            for (int j = 0; j < 4; j++) acc[mt][nb][j] = 0.f;

    const int krow = (lane & 7) + ((lane >> 4) << 3);
    const int csel = (lane & 8);
#pragma unroll
    for (int kc = 0; kc < 8; kc++) {
        const int kb = kc * 16;
        uint32_t a[2][4], bb[2][4];
#pragma unroll
        for (int mt = 0; mt < 2; mt++) {
            const uint32_t ad = sbase + KV_KF
                + (uint32_t)((kb + krow) * 272 + (m_base + mt * 16 + csel) * 2);
            LDSM4T(a[mt], ad);
        }
#pragma unroll
        for (int nt = 0; nt < 2; nt++) {
            const uint32_t bd = sbase + KV_VV
                + (uint32_t)((kb + krow) * 144 + (n_base + nt * 16 + csel) * 2);
            LDSM4T(bb[nt], bd);
        }
#pragma unroll
        for (int mt = 0; mt < 2; mt++)
#pragma unroll
            for (int nt = 0; nt < 2; nt++) {
                MMA_F16(acc[mt][nt * 2],     a[mt], bb[nt][0], bb[nt][2]);
                MMA_F16(acc[mt][nt * 2 + 1], a[mt], bb[nt][1], bb[nt][3]);
            }
    }

    __half* KVp = g_kvp + (size_t)pbase * 8192;
    const int r0 = lane >> 2, cq = (lane & 3) * 2;
#pragma unroll
    for (int mt = 0; mt < 2; mt++)
#pragma unroll
        for (int nb = 0; nb < 4; nb++) {
            const int i0 = m_base + mt * 16 + r0;
            const int j = n_base + nb * 8 + cq;
            *(__half2*)(KVp + i0 * 64 + j) =
                __floats2half2_rn(acc[mt][nb][0], acc[mt][nb][1]);
            *(__half2*)(KVp + (i0 + 8) * 64 + j) =
                __floats2half2_rn(acc[mt][nb][2], acc[mt][nb][3]);
        }
}

// combine partials; derive P1/P2/Q; emit kv^T fp16 for the apply MMA
__global__ __launch_bounds__(256) void kv_combine() {
    const int bh = blockIdx.x;
    const int t = threadIdx.x;

    __shared__ float kv_s[128 * 64];
    __shared__ float ksum_s[128];
    __shared__ float sv_s[64], cv_s[64];

    {
        float s[32];
#pragma unroll
        for (int i = 0; i < 32; i++) s[i] = 0.f;
        const int e0 = t * 32;
#pragma unroll
        for (int p = 0; p < NSPLIT; p++) {
            const __half* base = g_kvp + (size_t)(p * NBH + bh) * 8192 + e0;
#pragma unroll
            for (int c = 0; c < 4; c++) {
                uint4 u = *(const uint4*)(base + c * 8);
                float2 f;
                f = __half22float2(*(__half2*)&u.x); s[c*8+0] += f.x; s[c*8+1] += f.y;
                f = __half22float2(*(__half2*)&u.y); s[c*8+2] += f.x; s[c*8+3] += f.y;
                f = __half22float2(*(__half2*)&u.z); s[c*8+4] += f.x; s[c*8+5] += f.y;
                f = __half22float2(*(__half2*)&u.w); s[c*8+6] += f.x; s[c*8+7] += f.y;
            }
        }
#pragma unroll
        for (int c = 0; c < 8; c++)
            *(float4*)(kv_s + e0 + c * 4) =
                make_float4(s[c*4], s[c*4+1], s[c*4+2], s[c*4+3]);
    }
    if (t < 128) {
        float s = 0.f;
#pragma unroll
        for (int p = 0; p < NSPLIT; p++) s += g_ksump[(p * NBH + bh) * 128 + t];
        ksum_s[t] = s;
        g_ksum[bh * 128 + t] = s;
    } else if (t < 192) {
        float s = 0.f;
#pragma unroll
        for (int p = 0; p < NSPLIT; p++) s += g_svp[(p * NBH + bh) * 64 + t - 128];
        sv_s[t - 128] = s;
    } else {
        float s = 0.f;
#pragma unroll
        for (int p = 0; p < NSPLIT; p++) s += g_cvp[(p * NBH + bh) * 64 + t - 192];
        cv_s[t - 192] = s;
    }
    __syncthreads();

    {
        const int j = t & 63;
        const int i0 = (t >> 6) * 32;
        __half* Of = g_kvtf + (size_t)bh * 8192 + j * 128;
#pragma unroll 4
        for (int i = i0; i < i0 + 32; i += 2) {
            float a = kv_s[i * 64 + j];
            float c = kv_s[(i + 1) * 64 + j];
            *(__half2*)(Of + i) = __floats2half2_rn(a, c);
        }
    }

    if (t < 64) {
        float ks1 = 0.f;
#pragma unroll 8
        for (int i = 0; i < 64; i++) ks1 += kv_s[i * 64 + t];
        g_P1[bh * 64 + t] = 63.f * sv_s[t] - ks1;
    } else if (t < 128) {
        const int j = t - 64;
        float ks2 = 0.f;
#pragma unroll 8
        for (int i = 64; i < 128; i++) ks2 += kv_s[i * 64 + j];
        g_P2[bh * 64 + j] = 63.f * cv_s[j] - ks2;
    } else if (t == 128) {
        float s1k = 0.f;
        for (int i = 0; i < 64; i++) s1k += ksum_s[i];
        float ss = 0.f;
        for (int p = 0; p < NSPLIT; p++) ss += g_scp[(p * NBH + bh) * 2];
        g_Q[bh * 2] = 63.f * ss - s1k;
    } else if (t == 129) {
        float s2k = 0.f;
        for (int i = 64; i < 128; i++) s2k += ksum_s[i];
        float cc = 0.f;
        for (int p = 0; p < NSPLIT; p++) cc += g_scp[(p * NBH + bh) * 2 + 1];
        g_Q[bh * 2 + 1] = 63.f * cc - s2k;
    }
}

// ---------------- apply via fp16 HMMA: C = qf @ kv^T, then normalize -------
#define OFF_QF   0
#define OFF_KT   34816
#define OFF_KSUM 52224
#define OFF_P1   (OFF_KSUM + 512)
#define OFF_P2   (OFF_P1 + 256)
#define OFF_ZZ   (OFF_P2 + 256)
#define OFF_Z2   (OFF_ZZ + 512)
#define OFF_SN   (OFF_Z2 + 512)
#define OFF_CS   (OFF_SN + 512)
#define ATTN_SMEM (OFF_CS + 512)   // 55296

__global__ __launch_bounds__(256) void attn_apply() {
    extern __shared__ char sm[];
    const uint32_t sbase = (uint32_t)__cvta_generic_to_shared(sm);
    const int bh = blockIdx.x;
    const int b = bh / H_, h = bh % H_;
    const int lbase = blockIdx.y * 128;
    const int t = threadIdx.x;
    const int w = t >> 5, lane = t & 31;

    float* ksum_s = (float*)(sm + OFF_KSUM);
    float* P1_s   = (float*)(sm + OFF_P1);
    float* P2_s   = (float*)(sm + OFF_P2);
    float* zz_s   = (float*)(sm + OFF_ZZ);
    float* z2_s   = (float*)(sm + OFF_Z2);
    float* sn_s   = (float*)(sm + OFF_SN);
    float* cs_s   = (float*)(sm + OFF_CS);

    {
        const __half* qfb = g_qff + (((size_t)b * L_ + lbase) * H_ + h) * 128;
#pragma unroll
        for (int i = 0; i < 8; i++) {
            const int c = i * 256 + t;
            const int row = c >> 4, ch = c & 15;
            CP16(sbase + OFF_QF + row * 272 + ch * 16, qfb + (size_t)row * 2048 + ch * 8);
        }
        const __half* Gf = g_kvtf + (size_t)bh * 8192;
#pragma unroll
        for (int i = 0; i < 4; i++) {
            const int c = i * 256 + t;
            const int row = c >> 4, ch = c & 15;
            CP16(sbase + OFF_KT + row * 272 + ch * 16, Gf + c * 8);
        }
        asm volatile("cp.async.commit_group;" ::: "memory");
        if (t < 128) ksum_s[t] = g_ksum[bh * 128 + t];
        else if (t < 192) P1_s[t - 128] = g_P1[bh * 64 + t - 128];
        else P2_s[t - 192] = g_P2[bh * 64 + t - 192];
    }
    const float Q1 = g_Q[bh * 2], Q2 = g_Q[bh * 2 + 1];
    const float angk = PI_HALF / (float)L_;
    asm volatile("cp.async.wait_group 0;" ::: "memory");
    __syncthreads();

    const __half* qf = (const __half*)(sm + OFF_QF);

#pragma unroll 1
    for (int r = 0; r < 16; r++) {
        const int row = w * 16 + r;
        float f0 = __half2float(qf[row * 136 + lane]);
        float f1 = __half2float(qf[row * 136 + lane + 32]);
        float f2 = __half2float(qf[row * 136 + lane + 64]);
        float f3 = __half2float(qf[row * 136 + lane + 96]);
        float d1 = f0 * ksum_s[lane] + f1 * ksum_s[lane + 32] +
                   f2 * ksum_s[lane + 64] + f3 * ksum_s[lane + 96];
#pragma unroll
        for (int o = 16; o; o >>= 1) d1 += __shfl_xor_sync(0xffffffffu, d1, o);
        if (lane == 0) {
            float sn, cs;
            __sincosf(angk * (float)(lbase + row + 1), &sn, &cs);
            float z1 = 1.f / fmaxf(d1, 1e-6f);
            float d2 = sn * Q1 + cs * Q2 + d1;
            float z2 = 1.f / fmaxf(d2, 1e-6f);
            zz_s[row] = z1 + z2;
            z2_s[row] = z2;
            sn_s[row] = sn;
            cs_s[row] = cs;
        }
    }
    __syncthreads();

    const int m0 = w * 16;
    float acc[8][4];
#pragma unroll
    for (int nt = 0; nt < 8; nt++)
#pragma unroll
        for (int j = 0; j < 4; j++) acc[nt][j] = 0.f;

    const uint32_t aoffB = sbase + OFF_QF
        + (uint32_t)((m0 + (lane & 15)) * 272 + (lane >> 4) * 16);
    const uint32_t boffB = sbase + OFF_KT
        + (uint32_t)((lane & 15) * 272 + (lane >> 4) * 16);
#pragma unroll
    for (int ks = 0; ks < 8; ks++) {
        uint32_t a[4], bb[4][4];
        LDSM4(a, aoffB + ks * 32);
#pragma unroll
        for (int nt = 0; nt < 4; nt++)
            LDSM4(bb[nt], boffB + nt * 16 * 272 + ks * 32);
#pragma unroll
        for (int nt = 0; nt < 4; nt++) {
            MMA_F16(acc[nt * 2],     a, bb[nt][0], bb[nt][2]);
            MMA_F16(acc[nt * 2 + 1], a, bb[nt][1], bb[nt][3]);
        }
    }

    const int r0 = lane >> 2, cq = (lane & 3) * 2;
#pragma unroll
    for (int nt8 = 0; nt8 < 8; nt8++) {
        const int j = nt8 * 8 + cq;
        const float p1x = P1_s[j], p1y = P1_s[j + 1];
        const float p2x = P2_s[j], p2y = P2_s[j + 1];
#pragma unroll
        for (int half_ = 0; half_ < 2; half_++) {
            const int row = m0 + r0 + half_ * 8;
            const float oz = zz_s[row], o2 = z2_s[row];
            const float sr = sn_s[row], cr = cs_s[row];
            const float px = sr * p1x + cr * p2x;
            const float py = sr * p1y + cr * p2y;
            float o0 = oz * acc[nt8][half_ * 2 + 0] + o2 * px;
            float o1 = oz * acc[nt8][half_ * 2 + 1] + o2 * py;
            const int posl = lbase + row;
            const size_t oidx = ((size_t)posl * B_ + b) * E_ + h * D_ + j;
            *(__half2*)(g_af + oidx) = __floats2half2_rn(o0, o1);
        }
    }
}

// ---------------- launch ----------------------------------------------------
extern "C" void kernel_launch(void* const* d_in, const int* in_sizes, int n_in,
                              void* d_out, int out_size) {
    const float* X  = (const float*)d_in[0];
    const float* Wq = (const float*)d_in[1];
    const float* bq = (const float*)d_in[2];
    const float* Wk = (const float*)d_in[3];
    const float* bk = (const float*)d_in[4];
    const float* Wv = (const float*)d_in[5];
    const float* bv = (const float*)d_in[6];
    const float* Wo = (const float*)d_in[7];
    const float* bo = (const float*)d_in[8];
    float* out = (float*)d_out;

    cudaFuncSetAttribute(qkv_mma, cudaFuncAttributeMaxDynamicSharedMemorySize, DSMEM);
    cudaFuncSetAttribute(oproj_mma, cudaFuncAttributeMaxDynamicSharedMemorySize, DSMEM);
    cudaFuncSetAttribute(attn_apply, cudaFuncAttributeMaxDynamicSharedMemorySize, ATTN_SMEM);
    cudaFuncSetAttribute(kv_reduce_part, cudaFuncAttributeMaxDynamicSharedMemorySize, KV_SMEM);

    convert_x<<<(M_ * E_) / (256 * 4), 256>>>(X);
    convert_w<<<dim3(32, 32, 4), dim3(32, 8)>>>(Wq, Wk, Wv, Wo);
    qkv_mma<<<dim3(8, 128, 3), 256, DSMEM>>>(bq, bk, bv);
    kv_reduce_part<<<dim3(NBH, NSPLIT), 256, KV_SMEM>>>();
    kv_combine<<<NBH, 256>>>();
    attn_apply<<<dim3(NBH, L_ / 128), 256, ATTN_SMEM>>>();
    oproj_mma<<<dim3(8, 128), 256, DSMEM>>>(bo, out);
}

// round 16
// speedup vs baseline: 1.6726x; 1.0363x over previous
#include <cuda_runtime.h>
#include <cuda_bf16.h>
#include <cuda_fp16.h>
#include <cstdint>

// Problem constants
#define B_  8
#define L_  2048
#define E_  1024
#define H_  16
#define D_  64
#define M_  (B_ * L_)        // 16384 rows
#define NBH (B_ * H_)        // 128 head-batches
#define NSPLIT 16
#define LSPL (L_ / NSPLIT)   // 128
#define PI_HALF 1.5707963267948966f

// ---------------- device scratch (no allocations allowed) ----------------
__device__ __half g_qff[(size_t)M_ * H_ * 128];    // qf features, per-head
__device__ __half g_kff[(size_t)M_ * H_ * 128];    // kf features, per-head
__device__ __half g_vf[(size_t)M_ * H_ * 64];      // v fp16, per-head
__device__ __half g_xf[(size_t)M_ * E_];           // X fp16
__device__ __half g_af[(size_t)M_ * E_];           // attn out fp16 (rows l*B+b)
__device__ __half g_wtf[4ull * E_ * E_];           // W^T fp16, per matrix [n][k]
__device__ float g_ksum[NBH * 128];
__device__ float g_P1[NBH * 64];                   // 63*sv - KS1
__device__ float g_P2[NBH * 64];                   // 63*cv - KS2
__device__ float g_Q[NBH * 2];                     // 63*ssum-S1k, 63*csum-S2k
__device__ __half g_kvtf[(size_t)NBH * 80 * 128];  // kv^T [j][i] fp16; j=64 -> ksum, 65..79 zero
// split partials
__device__ __half g_kvp[(size_t)NSPLIT * NBH * 128 * 64];  // fp16 partials
__device__ float g_ksump[NSPLIT * NBH * 128];
__device__ float g_svp[NSPLIT * NBH * 64];
__device__ float g_cvp[NSPLIT * NBH * 64];
__device__ float g_scp[NSPLIT * NBH * 2];

// ---------------- PTX helpers ----------------------------------------------
#define CP16(dst, src) \
    asm volatile("cp.async.cg.shared.global [%0], [%1], 16;" :: "r"(dst), "l"(src))

#define LDSM4(r, addr) \
    asm volatile("ldmatrix.sync.aligned.m8n8.x4.shared.b16 {%0,%1,%2,%3}, [%4];" \
                 : "=r"((r)[0]), "=r"((r)[1]), "=r"((r)[2]), "=r"((r)[3]) : "r"(addr))

#define LDSM4T(r, addr) \
    asm volatile("ldmatrix.sync.aligned.m8n8.x4.trans.shared.b16 {%0,%1,%2,%3}, [%4];" \
                 : "=r"((r)[0]), "=r"((r)[1]), "=r"((r)[2]), "=r"((r)[3]) : "r"(addr))

#define MMA_F16(d, a, b0, b1) \
    asm volatile("mma.sync.aligned.m16n8k16.row.col.f32.f16.f16.f32 " \
                 "{%0,%1,%2,%3},{%4,%5,%6,%7},{%8,%9},{%0,%1,%2,%3};" \
                 : "+f"((d)[0]), "+f"((d)[1]), "+f"((d)[2]), "+f"((d)[3]) \
                 : "r"((a)[0]), "r"((a)[1]), "r"((a)[2]), "r"((a)[3]), \
                   "r"(b0), "r"(b1))

// ---------------- conversions ----------------------------------------------
__global__ __launch_bounds__(256) void convert_x(const float* __restrict__ X) {
    size_t i = ((size_t)blockIdx.x * 256 + threadIdx.x) * 4;
    float4 v = *(const float4*)(X + i);
    *(__half2*)(g_xf + i)     = __floats2half2_rn(v.x, v.y);
    *(__half2*)(g_xf + i + 2) = __floats2half2_rn(v.z, v.w);
}

// transpose: W[k][n] (fp32, n contiguous) -> WT[n][k] fp16
__global__ void convert_w(const float* __restrict__ Wq, const float* __restrict__ Wk,
                          const float* __restrict__ Wv, const float* __restrict__ Wo) {
    const float* W = (blockIdx.z == 0) ? Wq : (blockIdx.z == 1) ? Wk
                   : (blockIdx.z == 2) ? Wv : Wo;
    __shared__ float t[32][33];
    const int nb = blockIdx.x * 32, kb = blockIdx.y * 32;
    const int tx = threadIdx.x, ty = threadIdx.y;
#pragma unroll
    for (int i = 0; i < 4; i++)
        t[ty + 8 * i][tx] = W[(size_t)(kb + ty + 8 * i) * E_ + nb + tx];
    __syncthreads();
    __half* Of = g_wtf + (size_t)blockIdx.z * E_ * E_;
#pragma unroll
    for (int i = 0; i < 4; i++) {
        int n = nb + ty + 8 * i, k = kb + tx;
        Of[(size_t)n * E_ + k] = __float2half(t[tx][ty + 8 * i]);
    }
}

// ---- fp16 HMMA GEMM core: acc = A[128m] @ B^T[128n], BK=64, 3-stage ------
#define BK 64
#define STAGES 3
#define TROW 144                       // 64 fp16 = 128B + 16B pad
#define TILE_BYTES (128 * TROW)        // 18432
#define STAGE_B (2 * TILE_BYTES)       // 36864
#define DSMEM (STAGES * STAGE_B)       // 110592
#define NCHUNK 16

__device__ __forceinline__ void gemm_core(
    const __half* __restrict__ A, const __half* __restrict__ Bm,
    int mBase, int nBase, float acc[2][8][4])
{
    extern __shared__ char smem[];
    const uint32_t sbase = (uint32_t)__cvta_generic_to_shared(smem);
    const int tid = threadIdx.x;
    const int lane = tid & 31, wid = tid >> 5;
    const int wm = wid & 3, wn = wid >> 2;

    const __half* gp[8];
    uint32_t soff[8];
#pragma unroll
    for (int i = 0; i < 8; i++) {
        const int cid  = i * 256 + tid;
        const int tile = cid >> 10;
        const int ci   = cid & 1023;
        const int row  = ci >> 3;
        const int ch   = ci & 7;
        const __half* base = (tile == 0) ? A : Bm;
        const int grow = ((tile == 0) ? mBase : nBase) + row;
        gp[i]   = base + (size_t)grow * E_ + ch * 8;
        soff[i] = (uint32_t)(tile * TILE_BYTES + row * TROW + ch * 16);
    }

#pragma unroll
    for (int mt = 0; mt < 2; mt++)
#pragma unroll
        for (int nt = 0; nt < 8; nt++)
#pragma unroll
            for (int j = 0; j < 4; j++) acc[mt][nt][j] = 0.f;

#pragma unroll
    for (int c = 0; c < 2; c++) {
        const uint32_t sb = sbase + c * STAGE_B;
#pragma unroll
        for (int i = 0; i < 8; i++) CP16(sb + soff[i], gp[i] + c * BK);
        asm volatile("cp.async.commit_group;" ::: "memory");
    }

    for (int c = 0; c < NCHUNK; c++) {
        asm volatile("cp.async.wait_group 1;" ::: "memory");
        __syncthreads();

        if (c + 2 < NCHUNK) {
            const uint32_t sb = sbase + (uint32_t)(((c + 2) % STAGES) * STAGE_B);
            const size_t koff = (size_t)(c + 2) * BK;
#pragma unroll
            for (int i = 0; i < 8; i++) CP16(sb + soff[i], gp[i] + koff);
        }
        asm volatile("cp.async.commit_group;" ::: "memory");

        const uint32_t st = sbase + (uint32_t)((c % STAGES) * STAGE_B);
#pragma unroll
        for (int ks = 0; ks < 4; ks++) {
            uint32_t a[2][4], b[4][4];
            const uint32_t kof = (uint32_t)(ks * 32 + ((lane >> 4) << 4));
#pragma unroll
            for (int mt = 0; mt < 2; mt++) {
                const uint32_t ad = st + (uint32_t)((wm * 32 + mt * 16 + (lane & 15)) * TROW)
                                  + kof;
                LDSM4(a[mt], ad);
            }
#pragma unroll
            for (int nt = 0; nt < 4; nt++) {
                const uint32_t bd = st + TILE_BYTES
                                  + (uint32_t)((wn * 64 + nt * 16 + (lane & 15)) * TROW)
                                  + kof;
                LDSM4(b[nt], bd);
            }
#pragma unroll
            for (int mt = 0; mt < 2; mt++)
#pragma unroll
                for (int nt = 0; nt < 4; nt++) {
                    MMA_F16(acc[mt][nt * 2],     a[mt], b[nt][0], b[nt][2]);
                    MMA_F16(acc[mt][nt * 2 + 1], a[mt], b[nt][1], b[nt][3]);
                }
        }
    }
}

// qkv GEMM with fused softmax feature-map epilogue
__global__ __launch_bounds__(256, 2) void qkv_mma(const float* __restrict__ bq,
                                                  const float* __restrict__ bk,
                                                  const float* __restrict__ bv) {
    const int z = blockIdx.z;
    const float* bias = (z == 0) ? bq : (z == 1) ? bk : bv;
    const int mBase = blockIdx.y * 128, nBase = blockIdx.x * 128;

    float acc[2][8][4];
    gemm_core(g_xf, g_wtf + (size_t)z * E_ * E_, mBase, nBase, acc);

    const int tid = threadIdx.x;
    const int lane = tid & 31, wid = tid >> 5;
    const int wm = wid & 3, wn = wid >> 2;
    const int r0 = lane >> 2, cq = (lane & 3) * 2;
    const int head = blockIdx.x * 2 + wn;
    const float angk = PI_HALF / (float)L_;

    float2 bvs[8];
#pragma unroll
    for (int nt8 = 0; nt8 < 8; nt8++)
        bvs[nt8] = *(const float2*)(bias + nBase + wn * 64 + nt8 * 8 + cq);

    if (z < 2) {
        __half* gf = (z == 0) ? g_qff : g_kff;
#pragma unroll
        for (int mt = 0; mt < 2; mt++)
#pragma unroll
            for (int rh = 0; rh < 2; rh++) {
                const int row = mBase + wm * 32 + mt * 16 + r0 + rh * 8;
                float v[8][2];
                float m = -1e30f;
#pragma unroll
                for (int nt8 = 0; nt8 < 8; nt8++) {
                    v[nt8][0] = acc[mt][nt8][rh * 2 + 0] + bvs[nt8].x;
                    v[nt8][1] = acc[mt][nt8][rh * 2 + 1] + bvs[nt8].y;
                    m = fmaxf(m, fmaxf(v[nt8][0], v[nt8][1]));
                }
                m = fmaxf(m, __shfl_xor_sync(0xffffffffu, m, 1));
                m = fmaxf(m, __shfl_xor_sync(0xffffffffu, m, 2));
                float s = 0.f;
#pragma unroll
                for (int nt8 = 0; nt8 < 8; nt8++) {
                    v[nt8][0] = __expf(v[nt8][0] - m);
                    v[nt8][1] = __expf(v[nt8][1] - m);
                    s += v[nt8][0] + v[nt8][1];
                }
                s += __shfl_xor_sync(0xffffffffu, s, 1);
                s += __shfl_xor_sync(0xffffffffu, s, 2);
                const float inv = 1.f / s;
                const int l = row & (L_ - 1);
                float sn, cs;
                __sincosf(angk * (float)(l + 1), &sn, &cs);
                __half* base = gf + ((size_t)row * H_ + head) * 128;
#pragma unroll
                for (int nt8 = 0; nt8 < 8; nt8++) {
                    const int j = nt8 * 8 + cq;
                    const float a0 = v[nt8][0] * inv, a1 = v[nt8][1] * inv;
                    *(__half2*)(base + j)      = __floats2half2_rn(a0 * sn, a1 * sn);
                    *(__half2*)(base + j + 64) = __floats2half2_rn(a0 * cs, a1 * cs);
                }
            }
    } else {
#pragma unroll
        for (int mt = 0; mt < 2; mt++)
#pragma unroll
            for (int nt8 = 0; nt8 < 8; nt8++) {
                const int j = nt8 * 8 + cq;
                const int row = mBase + wm * 32 + mt * 16 + r0;
                __half* p0 = g_vf + ((size_t)row * H_ + head) * 64 + j;
                *(__half2*)p0 = __floats2half2_rn(acc[mt][nt8][0] + bvs[nt8].x,
                                                  acc[mt][nt8][1] + bvs[nt8].y);
                __half* p1 = g_vf + ((size_t)(row + 8) * H_ + head) * 64 + j;
                *(__half2*)p1 = __floats2half2_rn(acc[mt][nt8][2] + bvs[nt8].x,
                                                  acc[mt][nt8][3] + bvs[nt8].y);
            }
    }
}

__global__ __launch_bounds__(256, 2) void oproj_mma(const float* __restrict__ bo,
                                                    float* __restrict__ out) {
    const int mBase = blockIdx.y * 128, nBase = blockIdx.x * 128;
    float acc[2][8][4];
    gemm_core(g_af, g_wtf + 3ull * E_ * E_, mBase, nBase, acc);

    const int tid = threadIdx.x;
    const int lane = tid & 31, wid = tid >> 5;
    const int wm = wid & 3, wn = wid >> 2;
    const int r0 = lane >> 2, cq = (lane & 3) * 2;
#pragma unroll
    for (int mt = 0; mt < 2; mt++)
#pragma unroll
        for (int nt8 = 0; nt8 < 8; nt8++) {
            const int col = nBase + wn * 64 + nt8 * 8 + cq;
            const float2 bv = *(const float2*)(bo + col);
            const int row = mBase + wm * 32 + mt * 16 + r0;
            float* cp0 = out + (size_t)row * E_ + col;
            *(float2*)cp0 = make_float2(acc[mt][nt8][0] + bv.x, acc[mt][nt8][1] + bv.y);
            float* cp1 = cp0 + 8 * E_;
            *(float2*)cp1 = make_float2(acc[mt][nt8][2] + bv.x, acc[mt][nt8][3] + bv.y);
        }
}

// ---------------- KV reduction via HMMA (split over L) ---------------------
#define KV_KF   0                      // 128 * 272 = 34816
#define KV_VV   34816                  // 128 * 144 = 18432 -> 53248
#define KV_SN   53248
#define KV_CS   53760
#define KV_SMEM 54272

__global__ __launch_bounds__(256) void kv_reduce_part() {
    extern __shared__ char sm[];
    const uint32_t sbase = (uint32_t)__cvta_generic_to_shared(sm);
    const int bh = blockIdx.x;
    const int sp = blockIdx.y;
    const int b = bh / H_, h = bh % H_;
    const int pbase = sp * NBH + bh;

    const int t = threadIdx.x;
    const int w = t >> 5, lane = t & 31;

    __half* kf_s = (__half*)(sm + KV_KF);
    __half* v_s  = (__half*)(sm + KV_VV);
    float* sn_s  = (float*)(sm + KV_SN);
    float* cs_s  = (float*)(sm + KV_CS);

    {
        const __half* kfb = g_kff + (((size_t)b * L_ + sp * LSPL) * H_ + h) * 128;
        const __half* vb  = g_vf  + (((size_t)b * L_ + sp * LSPL) * H_ + h) * 64;
#pragma unroll
        for (int i = 0; i < 8; i++) {
            const int c = i * 256 + t;
            const int row = c >> 4, ch = c & 15;
            CP16(sbase + KV_KF + row * 272 + ch * 16, kfb + (size_t)row * 2048 + ch * 8);
        }
#pragma unroll
        for (int i = 0; i < 4; i++) {
            const int c = i * 256 + t;
            const int row = c >> 3, ch = c & 7;
            CP16(sbase + KV_VV + row * 144 + ch * 16, vb + (size_t)row * 1024 + ch * 8);
        }
        asm volatile("cp.async.commit_group;" ::: "memory");
    }
    if (t < 128) {
        float sn, cs;
        __sincosf(PI_HALF / (float)L_ * (float)(sp * LSPL + t + 1), &sn, &cs);
        sn_s[t] = sn;
        cs_s[t] = cs;
    }
    asm volatile("cp.async.wait_group 0;" ::: "memory");
    __syncthreads();

    if (t < 128) {
        float s = 0.f;
#pragma unroll 8
        for (int row = 0; row < 128; row++)
            s += __half2float(kf_s[row * 136 + t]);
        g_ksump[pbase * 128 + t] = s;
        if (t < 2) {
            const float* src = (t == 0) ? sn_s : cs_s;
            float acc = 0.f;
#pragma unroll 8
            for (int row = 0; row < 128; row++) acc += src[row];
            g_scp[pbase * 2 + t] = acc;
        }
    } else if (t < 192) {
        const int col = t - 128;
        float s = 0.f;
#pragma unroll 8
        for (int row = 0; row < 128; row++)
            s += sn_s[row] * __half2float(v_s[row * 72 + col]);
        g_svp[pbase * 64 + col] = s;
    } else {
        const int col = t - 192;
        float s = 0.f;
#pragma unroll 8
        for (int row = 0; row < 128; row++)
            s += cs_s[row] * __half2float(v_s[row * 72 + col]);
        g_cvp[pbase * 64 + col] = s;
    }

    // phase 2: kv[i][j] = sum_l kf[l][i] v[l][j] via trans-ldmatrix MMA
    const int wm = w & 3, wn = w >> 2;
    const int m_base = wm * 32, n_base = wn * 32;
    float acc[2][4][4];
#pragma unroll
    for (int mt = 0; mt < 2; mt++)
#pragma unroll
        for (int nb = 0; nb < 4; nb++)
#pragma unroll
            for (int j = 0; j < 4; j++) acc[mt][nb][j] = 0.f;

    const int krow = (lane & 7) + ((lane >> 4) << 3);
    const int csel = (lane & 8);
#pragma unroll
    for (int kc = 0; kc < 8; kc++) {
        const int kb = kc * 16;
        uint32_t a[2][4], bb[2][4];
#pragma unroll
        for (int mt = 0; mt < 2; mt++) {
            const uint32_t ad = sbase + KV_KF
                + (uint32_t)((kb + krow) * 272 + (m_base + mt * 16 + csel) * 2);
            LDSM4T(a[mt], ad);
        }
#pragma unroll
        for (int nt = 0; nt < 2; nt++) {
            const uint32_t bd = sbase + KV_VV
                + (uint32_t)((kb + krow) * 144 + (n_base + nt * 16 + csel) * 2);
            LDSM4T(bb[nt], bd);
        }
#pragma unroll
        for (int mt = 0; mt < 2; mt++)
#pragma unroll
            for (int nt = 0; nt < 2; nt++) {
                MMA_F16(acc[mt][nt * 2],     a[mt], bb[nt][0], bb[nt][2]);
                MMA_F16(acc[mt][nt * 2 + 1], a[mt], bb[nt][1], bb[nt][3]);
            }
    }

    __half* KVp = g_kvp + (size_t)pbase * 8192;
    const int r0 = lane >> 2, cq = (lane & 3) * 2;
#pragma unroll
    for (int mt = 0; mt < 2; mt++)
#pragma unroll
        for (int nb = 0; nb < 4; nb++) {
            const int i0 = m_base + mt * 16 + r0;
            const int j = n_base + nb * 8 + cq;
            *(__half2*)(KVp + i0 * 64 + j) =
                __floats2half2_rn(acc[mt][nb][0], acc[mt][nb][1]);
            *(__half2*)(KVp + (i0 + 8) * 64 + j) =
                __floats2half2_rn(acc[mt][nb][2], acc[mt][nb][3]);
        }
}

// combine partials; derive P1/P2/Q; emit kv^T fp16 (+ksum row, zero pad)
__global__ __launch_bounds__(256) void kv_combine() {
    const int bh = blockIdx.x;
    const int t = threadIdx.x;

    __shared__ float kv_s[128 * 64];
    __shared__ float ksum_s[128];
    __shared__ float sv_s[64], cv_s[64];

    {
        float s[32];
#pragma unroll
        for (int i = 0; i < 32; i++) s[i] = 0.f;
        const int e0 = t * 32;
#pragma unroll
        for (int p = 0; p < NSPLIT; p++) {
            const __half* base = g_kvp + (size_t)(p * NBH + bh) * 8192 + e0;
#pragma unroll
            for (int c = 0; c < 4; c++) {
                uint4 u = *(const uint4*)(base + c * 8);
                float2 f;
                f = __half22float2(*(__half2*)&u.x); s[c*8+0] += f.x; s[c*8+1] += f.y;
                f = __half22float2(*(__half2*)&u.y); s[c*8+2] += f.x; s[c*8+3] += f.y;
                f = __half22float2(*(__half2*)&u.z); s[c*8+4] += f.x; s[c*8+5] += f.y;
                f = __half22float2(*(__half2*)&u.w); s[c*8+6] += f.x; s[c*8+7] += f.y;
            }
        }
#pragma unroll
        for (int c = 0; c < 8; c++)
            *(float4*)(kv_s + e0 + c * 4) =
                make_float4(s[c*4], s[c*4+1], s[c*4+2], s[c*4+3]);
    }
    if (t < 128) {
        float s = 0.f;
#pragma unroll
        for (int p = 0; p < NSPLIT; p++) s += g_ksump[(p * NBH + bh) * 128 + t];
        ksum_s[t] = s;
        g_ksum[bh * 128 + t] = s;
    } else if (t < 192) {
        float s = 0.f;
#pragma unroll
        for (int p = 0; p < NSPLIT; p++) s += g_svp[(p * NBH + bh) * 64 + t - 128];
        sv_s[t - 128] = s;
    } else {
        float s = 0.f;
#pragma unroll
        for (int p = 0; p < NSPLIT; p++) s += g_cvp[(p * NBH + bh) * 64 + t - 192];
        cv_s[t - 192] = s;
    }
    __syncthreads();

    {
        __half* Ob = g_kvtf + (size_t)bh * 10240;
        const int j = t & 63;
        const int i0 = (t >> 6) * 32;
        __half* Of = Ob + j * 128;
#pragma unroll 4
        for (int i = i0; i < i0 + 32; i += 2) {
            float a = kv_s[i * 64 + j];
            float c = kv_s[(i + 1) * 64 + j];
            *(__half2*)(Of + i) = __floats2half2_rn(a, c);
        }
        // row 64 = ksum
        if (t < 64)
            *(__half2*)(Ob + 64 * 128 + t * 2) =
                __floats2half2_rn(ksum_s[t * 2], ksum_s[t * 2 + 1]);
        // rows 65..79 = zero
        for (int idx = t; idx < 960; idx += 256)
            *(__half2*)(Ob + 65 * 128 + idx * 2) = __floats2half2_rn(0.f, 0.f);
    }

    if (t < 64) {
        float ks1 = 0.f;
#pragma unroll 8
        for (int i = 0; i < 64; i++) ks1 += kv_s[i * 64 + t];
        g_P1[bh * 64 + t] = 63.f * sv_s[t] - ks1;
    } else if (t < 128) {
        const int j = t - 64;
        float ks2 = 0.f;
#pragma unroll 8
        for (int i = 64; i < 128; i++) ks2 += kv_s[i * 64 + j];
        g_P2[bh * 64 + j] = 63.f * cv_s[j] - ks2;
    } else if (t == 128) {
        float s1k = 0.f;
        for (int i = 0; i < 64; i++) s1k += ksum_s[i];
        float ss = 0.f;
        for (int p = 0; p < NSPLIT; p++) ss += g_scp[(p * NBH + bh) * 2];
        g_Q[bh * 2] = 63.f * ss - s1k;
    } else if (t == 129) {
        float s2k = 0.f;
        for (int i = 64; i < 128; i++) s2k += ksum_s[i];
        float cc = 0.f;
        for (int p = 0; p < NSPLIT; p++) cc += g_scp[(p * NBH + bh) * 2 + 1];
        g_Q[bh * 2 + 1] = 63.f * cc - s2k;
    }
}

// ---------- apply via fp16 HMMA: C = qf @ [kv^T | ksum], normalize ---------
#define OFF_QF   0                 // 128 * 272 = 34816
#define OFF_KT   34816             // 80 * 272 = 21760 -> 56576
#define OFF_P1   56576             // 256B
#define OFF_P2   56832             // 256B
#define ATTN_SMEM 57088

__global__ __launch_bounds__(256) void attn_apply() {
    extern __shared__ char sm[];
    const uint32_t sbase = (uint32_t)__cvta_generic_to_shared(sm);
    const int bh = blockIdx.x;
    const int b = bh / H_, h = bh % H_;
    const int lbase = blockIdx.y * 128;
    const int t = threadIdx.x;
    const int w = t >> 5, lane = t & 31;

    float* P1_s = (float*)(sm + OFF_P1);
    float* P2_s = (float*)(sm + OFF_P2);

    {
        const __half* qfb = g_qff + (((size_t)b * L_ + lbase) * H_ + h) * 128;
#pragma unroll
        for (int i = 0; i < 8; i++) {
            const int c = i * 256 + t;
            const int row = c >> 4, ch = c & 15;
            CP16(sbase + OFF_QF + row * 272 + ch * 16, qfb + (size_t)row * 2048 + ch * 8);
        }
        const __half* Gf = g_kvtf + (size_t)bh * 10240;
#pragma unroll
        for (int i = 0; i < 5; i++) {
            const int c = i * 256 + t;
            const int row = c >> 4, ch = c & 15;
            CP16(sbase + OFF_KT + row * 272 + ch * 16, Gf + c * 8);
        }
        asm volatile("cp.async.commit_group;" ::: "memory");
        if (t < 64) P1_s[t] = g_P1[bh * 64 + t];
        else if (t < 128) P2_s[t - 64] = g_P2[bh * 64 + t - 64];
    }
    const float Q1 = g_Q[bh * 2], Q2 = g_Q[bh * 2 + 1];
    const float angk = PI_HALF / (float)L_;
    asm volatile("cp.async.wait_group 0;" ::: "memory");
    __syncthreads();

    const int m0 = w * 16;
    float acc[9][4];
#pragma unroll
    for (int nt = 0; nt < 9; nt++)
#pragma unroll
        for (int j = 0; j < 4; j++) acc[nt][j] = 0.f;

    const uint32_t aoffB = sbase + OFF_QF
        + (uint32_t)((m0 + (lane & 15)) * 272 + (lane >> 4) * 16);
    const uint32_t boffB = sbase + OFF_KT
        + (uint32_t)((lane & 15) * 272 + (lane >> 4) * 16);
#pragma unroll
    for (int ks = 0; ks < 8; ks++) {
        uint32_t a[4], bb[5][4];
        LDSM4(a, aoffB + ks * 32);
#pragma unroll
        for (int nt = 0; nt < 5; nt++)
            LDSM4(bb[nt], boffB + nt * 16 * 272 + ks * 32);
#pragma unroll
        for (int nt = 0; nt < 4; nt++) {
            MMA_F16(acc[nt * 2],     a, bb[nt][0], bb[nt][2]);
            MMA_F16(acc[nt * 2 + 1], a, bb[nt][1], bb[nt][3]);
        }
        MMA_F16(acc[8], a, bb[4][0], bb[4][2]);   // cols 64-71 (64 = d1)
    }

    // broadcast d1 (col 64, held by quad-base lane) to all quad lanes
    const float d1a = __shfl_sync(0xffffffffu, acc[8][0], lane & ~3);
    const float d1b = __shfl_sync(0xffffffffu, acc[8][2], lane & ~3);
    const int r0 = lane >> 2, cq = (lane & 3) * 2;

    float sn0, cs0, sn1, cs1;
    __sincosf(angk * (float)(lbase + m0 + r0 + 1), &sn0, &cs0);
    __sincosf(angk * (float)(lbase + m0 + r0 + 9), &sn1, &cs1);
    const float z1a = 1.f / fmaxf(d1a, 1e-6f);
    const float z2a = 1.f / fmaxf(sn0 * Q1 + cs0 * Q2 + d1a, 1e-6f);
    const float z1b = 1.f / fmaxf(d1b, 1e-6f);
    const float z2b = 1.f / fmaxf(sn1 * Q1 + cs1 * Q2 + d1b, 1e-6f);
    const float oza = z1a + z2a, ozb = z1b + z2b;

#pragma unroll
    for (int nt8 = 0; nt8 < 8; nt8++) {
        const int j = nt8 * 8 + cq;
        const float p1x = P1_s[j], p1y = P1_s[j + 1];
        const float p2x = P2_s[j], p2y = P2_s[j + 1];
        {
            const int row = m0 + r0;
            const float px = sn0 * p1x + cs0 * p2x;
            const float py = sn0 * p1y + cs0 * p2y;
            float o0 = oza * acc[nt8][0] + z2a * px;
            float o1 = oza * acc[nt8][1] + z2a * py;
            const size_t oidx = ((size_t)(lbase + row) * B_ + b) * E_ + h * D_ + j;
            *(__half2*)(g_af + oidx) = __floats2half2_rn(o0, o1);
        }
        {
            const int row = m0 + r0 + 8;
            const float px = sn1 * p1x + cs1 * p2x;
            const float py = sn1 * p1y + cs1 * p2y;
            float o0 = ozb * acc[nt8][2] + z2b * px;
            float o1 = ozb * acc[nt8][3] + z2b * py;
            const size_t oidx = ((size_t)(lbase + row) * B_ + b) * E_ + h * D_ + j;
            *(__half2*)(g_af + oidx) = __floats2half2_rn(o0, o1);
        }
    }
}

// ---------------- launch ----------------------------------------------------
extern "C" void kernel_launch(void* const* d_in, const int* in_sizes, int n_in,
                              void* d_out, int out_size) {
    const float* X  = (const float*)d_in[0];
    const float* Wq = (const float*)d_in[1];
    const float* bq = (const float*)d_in[2];
    const float* Wk = (const float*)d_in[3];
    const float* bk = (const float*)d_in[4];
    const float* Wv = (const float*)d_in[5];
    const float* bv = (const float*)d_in[6];
    const float* Wo = (const float*)d_in[7];
    const float* bo = (const float*)d_in[8];
    float* out = (float*)d_out;

    cudaFuncSetAttribute(qkv_mma, cudaFuncAttributeMaxDynamicSharedMemorySize, DSMEM);
    cudaFuncSetAttribute(oproj_mma, cudaFuncAttributeMaxDynamicSharedMemorySize, DSMEM);
    cudaFuncSetAttribute(attn_apply, cudaFuncAttributeMaxDynamicSharedMemorySize, ATTN_SMEM);
    cudaFuncSetAttribute(kv_reduce_part, cudaFuncAttributeMaxDynamicSharedMemorySize, KV_SMEM);

    convert_x<<<(M_ * E_) / (256 * 4), 256>>>(X);
    convert_w<<<dim3(32, 32, 4), dim3(32, 8)>>>(Wq, Wk, Wv, Wo);
    qkv_mma<<<dim3(8, 128, 3), 256, DSMEM>>>(bq, bk, bv);
    kv_reduce_part<<<dim3(NBH, NSPLIT), 256, KV_SMEM>>>();
    kv_combine<<<NBH, 256>>>();
    attn_apply<<<dim3(NBH, L_ / 128), 256, ATTN_SMEM>>>();
    oproj_mma<<<dim3(8, 128), 256, DSMEM>>>(bo, out);
}